// round 17
// baseline (speedup 1.0000x reference)
#include <cuda_runtime.h>
#include <cuda_bf16.h>
#include <cstdint>

// ---------------- problem constants ----------------
#define BB 16
#define LL 4096
#define CC 256
#define DM 128            // d_model
#define DI 256            // d_inner
#define DS 16             // d_state
#define DR 8              // dt_rank
#define KCV 4             // conv kernel
#define TT (BB*LL)        // 65536 tokens
#define CH 128            // scan chunk length
#define NC (LL/CH)        // 32 chunks per batch

// ---------------- scratch (device globals; no allocation allowed) ----------------
__device__ __align__(16) float g_H  [(size_t)TT*DM];        // mix output (fp32)
__device__ __align__(16) float g_XZ [(size_t)TT*(2*DI)];    // in-proj output (xc_raw | z)
__device__ __align__(16) float g_XC [(size_t)TT*DI];        // conv+silu output
__device__ __align__(16) float g_DBL[(size_t)TT*40];        // xproj output
__device__ __align__(16) float g_Y  [(size_t)TT*DI];        // scan output (fp32)
__device__ __align__(16) float g_O1 [(size_t)TT*DM];        // op output (fp32)
// transposed + split weights: Wt[n,k] = W[k,n]
__device__ __align__(16) __nv_bfloat16 g_Wmix_h[DM*512],  g_Wmix_l[DM*512];
__device__ __align__(16) __nv_bfloat16 g_Win_h [512*DM],  g_Win_l [512*DM];
__device__ __align__(16) __nv_bfloat16 g_Wxp_h [64*DI],   g_Wxp_l [64*DI];
__device__ __align__(16) __nv_bfloat16 g_Wop_h [DM*DI],   g_Wop_l [DM*DI];
__device__ __align__(16) __nv_bfloat16 g_Wout_h[CC*DM],   g_Wout_l[CC*DM];
// scan scratch
__device__ float g_Hend[(size_t)BB*NC*DI*DS];
__device__ float g_Hin [(size_t)BB*NC*DI*DS];
__device__ float g_S   [(size_t)BB*NC*DI];
__device__ float g_A   [DI*DS];
__device__ int   g_Aflag[DI];

// ---------------- PTX helpers (sm_80-compatible; no 'a'-suffix features) ----------------
__device__ __forceinline__ uint32_t smem_to_u32(const void* p) {
    uint32_t a;
    asm("{ .reg .u64 t; cvta.to.shared.u64 t, %1; cvt.u32.u64 %0, t; }" : "=r"(a) : "l"(p));
    return a;
}
__device__ __forceinline__ void cp16(uint32_t s, const void* g) {
    asm volatile("cp.async.cg.shared.global [%0], [%1], 16;" :: "r"(s), "l"(g));
}
#define CP_COMMIT() asm volatile("cp.async.commit_group;" ::: "memory")
#define CP_WAIT(n)  asm volatile("cp.async.wait_group %0;" :: "n"(n) : "memory")

#define LDSM_X4(r, addr) \
    asm volatile("ldmatrix.sync.aligned.m8n8.x4.shared.b16 {%0,%1,%2,%3}, [%4];" \
        : "=r"((r)[0]), "=r"((r)[1]), "=r"((r)[2]), "=r"((r)[3]) : "r"(addr))

#define MMA16816(d, a, b0, b1) \
    asm volatile("mma.sync.aligned.m16n8k16.row.col.f32.bf16.bf16.f32 " \
        "{%0,%1,%2,%3}, {%4,%5,%6,%7}, {%8,%9}, {%0,%1,%2,%3};" \
        : "+f"((d)[0]), "+f"((d)[1]), "+f"((d)[2]), "+f"((d)[3]) \
        : "r"((a)[0]), "r"((a)[1]), "r"((a)[2]), "r"((a)[3]), "r"(b0), "r"(b1))

// ---------------- packed f32x2 helpers (scan) ----------------
__device__ __forceinline__ unsigned long long pack2(float lo, float hi){
    unsigned long long r; asm("mov.b64 %0,{%1,%2};" : "=l"(r) : "f"(lo), "f"(hi)); return r;
}
__device__ __forceinline__ float2 unpack2(unsigned long long v){
    float2 r; asm("mov.b64 {%0,%1},%2;" : "=f"(r.x), "=f"(r.y) : "l"(v)); return r;
}
__device__ __forceinline__ unsigned long long mul2(unsigned long long a, unsigned long long b){
    unsigned long long d; asm("mul.rn.f32x2 %0,%1,%2;" : "=l"(d) : "l"(a), "l"(b)); return d;
}
__device__ __forceinline__ unsigned long long fma2(unsigned long long a, unsigned long long b, unsigned long long c){
    unsigned long long d; asm("fma.rn.f32x2 %0,%1,%2,%3;" : "=l"(d) : "l"(a), "l"(b), "l"(c)); return d;
}

__device__ __forceinline__ void split_bf16(float v, __nv_bfloat16& h, __nv_bfloat16& l) {
    h = __float2bfloat16(v);
    l = __float2bfloat16(v - __bfloat162float(h));
}
__device__ __forceinline__ uint32_t pack_bf(__nv_bfloat16 a, __nv_bfloat16 b) {
    uint16_t ua = *reinterpret_cast<uint16_t*>(&a);
    uint16_t ub = *reinterpret_cast<uint16_t*>(&b);
    return (uint32_t)ua | ((uint32_t)ub << 16);
}
// inline softplus for dt
__device__ __forceinline__ float softplus_f(float a) {
    return (a > 15.f) ? a : __logf(1.f + __expf(a));
}

// =====================================================================
// mma.sync split GEMM, fp32 A in global: C[m,n] = sum_k A[m,k]*Wt[n,k] + bias
// Per K=32 chunk: load A fp32 ONCE (register-staged), split to Ah/Al smem;
// cp.async pre-split weight tiles Bh/Bl; 3 segment MMA passes
// (Ah*Bh + Ah*Bl + Al*Bh) from one smem residency. fp32 accumulate.
// CTA: 64 x NT tile, 8 warps (2x4), warp tile 32 x NT/4, double-buffered.
// 2 CTAs/SM so one CTA's MMAs cover the other's split/sync sections.
// =====================================================================
template<int NT, bool CONCAT>
__global__ __launch_bounds__(256, 2)
void gemm_mma(const float* __restrict__ A0, const float* __restrict__ A1,
              const __nv_bfloat16* __restrict__ Bh, const __nv_bfloat16* __restrict__ Bl,
              const float* __restrict__ bias, float* __restrict__ Cf,
              int K, int Nout, int Nclip)
{
    constexpr int NTW = NT / 4;          // warp n-tile: 32 or 16
    constexpr int NF  = NTW / 8;         // n-frags per warp: 4 or 2
    constexpr int LDA = 40;              // padded row (elements)
    constexpr uint32_t ABUF = 64*LDA*2;  // bytes per A buffer (5120)
    constexpr uint32_t BBUF = NT*LDA*2;  // bytes per B buffer

    extern __shared__ char dsm[];
    const uint32_t sAh = smem_to_u32(dsm);
    const uint32_t sAl = sAh + 2*ABUF;
    const uint32_t sBh = sAl + 2*ABUF;
    const uint32_t sBl = sBh + 2*BBUF;

    const int tid  = threadIdx.x;
    const int lane = tid & 31;
    const int w    = tid >> 5;
    const int wm   = w >> 2;             // 0..1 -> 32-row halves
    const int wn   = w & 3;
    const int m0   = blockIdx.x * 64;
    const int n0   = blockIdx.y * NT;

    float acc[2][NF][4];
#pragma unroll
    for (int i = 0; i < 2; i++)
#pragma unroll
        for (int j = 0; j < NF; j++)
#pragma unroll
            for (int e = 0; e < 4; e++) acc[i][j][e] = 0.f;

    const int NCH = K >> 5;              // K=32 chunks
    float4 av[2];                        // register-staged A chunk (8 fp32/thread)

    // ---- loaders ----
    auto ldg_A = [&](int kk) {
        const int k0 = kk << 5;
#pragma unroll
        for (int q = 0; q < 2; ++q) {
            int c = tid + q*256;
            int row = c >> 3, sg = c & 7;
            int gk = k0 + sg*4;
            const float* src;
            if (CONCAT) src = (gk < 256) ? A0 + (size_t)(m0+row)*256 + gk
                                         : A1 + (size_t)(m0+row)*256 + (gk-256);
            else        src = A0 + (size_t)(m0+row)*K + gk;
            av[q] = *reinterpret_cast<const float4*>(src);
        }
    };
    auto sts_A = [&](int buf) {
#pragma unroll
        for (int q = 0; q < 2; ++q) {
            int c = tid + q*256;
            int row = c >> 3, sg = c & 7;
            __nv_bfloat16 h0,l0,h1,l1,h2,l2,h3,l3;
            split_bf16(av[q].x, h0, l0); split_bf16(av[q].y, h1, l1);
            split_bf16(av[q].z, h2, l2); split_bf16(av[q].w, h3, l3);
            uint32_t off = (uint32_t)(row*LDA + sg*4)*2;
            uint2 hv = { pack_bf(h0,h1), pack_bf(h2,h3) };
            uint2 lv = { pack_bf(l0,l1), pack_bf(l2,l3) };
            *reinterpret_cast<uint2*>(dsm + buf*ABUF + off) = hv;
            *reinterpret_cast<uint2*>(dsm + 2*ABUF + buf*ABUF + off) = lv;
        }
    };
    auto cpa_B = [&](int kk, int buf) {
        const int k0 = kk << 5;
#pragma unroll
        for (int q = 0; q < NT/64; ++q) {
            int c = tid + q*256;
            int row = c >> 2, sg = c & 3;
            cp16(sBh + buf*BBUF + (uint32_t)(row*LDA + sg*8)*2,
                 Bh + (size_t)(n0+row)*K + k0 + sg*8);
        }
#pragma unroll
        for (int q = 0; q < NT/64; ++q) {
            int c = tid + q*256;
            int row = c >> 2, sg = c & 3;
            cp16(sBl + buf*BBUF + (uint32_t)(row*LDA + sg*8)*2,
                 Bl + (size_t)(n0+row)*K + k0 + sg*8);
        }
        CP_COMMIT();
    };

    // ---- prologue: chunk 0 into buf 0 ----
    ldg_A(0);
    cpa_B(0, 0);
    sts_A(0);
    CP_WAIT(0);
    __syncthreads();

    int buf = 0;
#pragma unroll 1
    for (int it = 0; it < NCH; ++it) {
        const bool more = (it + 1 < NCH);
        if (more) { ldg_A(it + 1); cpa_B(it + 1, buf ^ 1); }

        // ---- compute: 3 segments from this chunk ----
#pragma unroll
        for (int ks = 0; ks < 2; ++ks) {
            uint32_t a[2][4];
            uint32_t bh[NF][2], bl[NF][2];
#pragma unroll
            for (int mf = 0; mf < 2; ++mf) {
                uint32_t addr = sAh + buf*ABUF +
                    (uint32_t)((wm*32 + mf*16 + (lane & 15))*LDA + ks*16 + ((lane >> 4) << 3))*2;
                LDSM_X4(a[mf], addr);
            }
#pragma unroll
            for (int nf2 = 0; nf2 < NF/2; ++nf2) {
                uint32_t r[4];
                uint32_t addr = sBh + buf*BBUF +
                    (uint32_t)((wn*NTW + nf2*16 + ((lane >> 4) << 3) + (lane & 7))*LDA
                               + ks*16 + (((lane >> 3) & 1) << 3))*2;
                LDSM_X4(r, addr);
                bh[2*nf2][0] = r[0]; bh[2*nf2][1] = r[1];
                bh[2*nf2+1][0] = r[2]; bh[2*nf2+1][1] = r[3];
            }
#pragma unroll
            for (int nf2 = 0; nf2 < NF/2; ++nf2) {
                uint32_t r[4];
                uint32_t addr = sBl + buf*BBUF +
                    (uint32_t)((wn*NTW + nf2*16 + ((lane >> 4) << 3) + (lane & 7))*LDA
                               + ks*16 + (((lane >> 3) & 1) << 3))*2;
                LDSM_X4(r, addr);
                bl[2*nf2][0] = r[0]; bl[2*nf2][1] = r[1];
                bl[2*nf2+1][0] = r[2]; bl[2*nf2+1][1] = r[3];
            }
            // seg0: Ah*Bh ; seg1: Ah*Bl
#pragma unroll
            for (int mf = 0; mf < 2; ++mf)
#pragma unroll
                for (int nf = 0; nf < NF; ++nf) {
                    MMA16816(acc[mf][nf], a[mf], bh[nf][0], bh[nf][1]);
                    MMA16816(acc[mf][nf], a[mf], bl[nf][0], bl[nf][1]);
                }
            // seg2: Al*Bh (reload a from Al)
#pragma unroll
            for (int mf = 0; mf < 2; ++mf) {
                uint32_t addr = sAl + buf*ABUF +
                    (uint32_t)((wm*32 + mf*16 + (lane & 15))*LDA + ks*16 + ((lane >> 4) << 3))*2;
                LDSM_X4(a[mf], addr);
            }
#pragma unroll
            for (int mf = 0; mf < 2; ++mf)
#pragma unroll
                for (int nf = 0; nf < NF; ++nf)
                    MMA16816(acc[mf][nf], a[mf], bh[nf][0], bh[nf][1]);
        }

        if (more) {
            sts_A(buf ^ 1);
            CP_WAIT(0);
            __syncthreads();
            buf ^= 1;
        }
    }

    // ---- epilogue (fp32 + bias) ----
#pragma unroll
    for (int mf = 0; mf < 2; ++mf) {
        const int r0 = m0 + wm*32 + mf*16 + (lane >> 2);
#pragma unroll
        for (int nf = 0; nf < NF; ++nf) {
            const int c0 = n0 + wn*NTW + nf*8 + ((lane & 3) << 1);
#pragma unroll
            for (int half = 0; half < 2; ++half) {
                const int row = r0 + half*8;
                if (c0 < Nclip)
                    Cf[(size_t)row*Nout + c0]     = acc[mf][nf][2*half]   + (bias ? bias[c0]   : 0.f);
                if (c0 + 1 < Nclip)
                    Cf[(size_t)row*Nout + c0 + 1] = acc[mf][nf][2*half+1] + (bias ? bias[c0+1] : 0.f);
            }
        }
    }
}

// ---------------- prep kernels ----------------
__global__ __launch_bounds__(256)
void wprep_kernel(const float* __restrict__ W, __nv_bfloat16* __restrict__ Wh,
                  __nv_bfloat16* __restrict__ Wl, int K, int N, int NP)
{
    int idx = blockIdx.x*256 + threadIdx.x;
    if (idx >= NP*K) return;
    int n = idx / K, k = idx % K;
    float v = (n < N) ? W[(size_t)k*N + n] : 0.f;
    __nv_bfloat16 h, l; split_bf16(v, h, l);
    Wh[idx] = h; Wl[idx] = l;
}

// ---------------- A_log preprocessing ----------------
__global__ void aprep_kernel(const float* __restrict__ A_log)
{
    int d = threadIdx.x;
    if (d >= DI) return;
    float Av[DS];
#pragma unroll
    for (int s = 0; s < DS; s++) { Av[s] = -__expf(A_log[d*DS + s]); g_A[d*DS + s] = Av[s]; }
    int ok = 1;
#pragma unroll
    for (int s = 0; s < DS; s++) {
        float tgt = Av[0] * (float)(s+1);
        if (fabsf(Av[s] - tgt) > 1e-5f * fabsf(Av[s]) + 1e-7f) ok = 0;
    }
    g_Aflag[d] = ok;
}

// ---------------- depthwise conv (K=4, causal) + SiLU ----------------
__global__ __launch_bounds__(256)
void conv_silu_kernel(const float* __restrict__ conv_w, const float* __restrict__ conv_b)
{
    int idx = blockIdx.x * 256 + threadIdx.x;   // over T*DI
    int d = idx & (DI-1);
    int t = idx >> 8;
    int l = t & (LL-1);
    float acc = conv_b[d];
#pragma unroll
    for (int k = 0; k < KCV; k++) {
        int lt = l - (KCV-1) + k;
        if (lt >= 0) acc += g_XZ[(size_t)(t - (KCV-1) + k)*(2*DI) + d] * conv_w[d*KCV + k];
    }
    float sig = 1.f / (1.f + __expf(-acc));
    g_XC[idx] = acc * sig;
}

// ---------------- scan pass 1 (dt computed inline from DBL) ----------------
__global__ __launch_bounds__(256)
void scan_pass1(const float* __restrict__ W_dt, const float* __restrict__ b_dt)
{
    __shared__ float sB[CH][DS];
    __shared__ float sR[CH][DR];
    const int bc = blockIdx.x;
    const int b = bc / NC, c = bc % NC;
    const int d = threadIdx.x;
    const int tok0 = b*LL + c*CH;

#pragma unroll
    for (int q = 0; q < (CH*DS)/256; q++) {
        int e = threadIdx.x + q*256;
        int j = e % DS, st = e / DS;
        sB[st][j] = g_DBL[(size_t)(tok0+st)*40 + 8 + j];
    }
#pragma unroll
    for (int q = 0; q < (CH*DR)/256; q++) {
        int e = threadIdx.x + q*256;
        int r = e & (DR-1), st = e >> 3;
        sR[st][r] = g_DBL[(size_t)(tok0+st)*40 + r];
    }
    __syncthreads();

    float wdt[DR];
#pragma unroll
    for (int r = 0; r < DR; r++) wdt[r] = W_dt[r*DI + d];
    const float bdt = b_dt[d];

    const float A0 = g_A[d*DS];
    const int fast = g_Aflag[d];
    float S = 0.f;

    if (fast) {
        unsigned long long h2[DS/2];
#pragma unroll
        for (int sp = 0; sp < DS/2; sp++) h2[sp] = 0ULL;
        for (int st = 0; st < CH; st++) {
            float aa = bdt;
#pragma unroll
            for (int r = 0; r < DR; r++) aa += sR[st][r] * wdt[r];
            float dt = softplus_f(aa);
            float x  = g_XC[(size_t)(tok0+st)*DI + d];
            S += dt;
            float e1 = __expf(dt * A0);
            float e2 = e1 * e1;
            unsigned long long p2  = pack2(e1, e2);
            unsigned long long e22 = pack2(e2, e2);
            float dtx = dt * x;
            unsigned long long dtx2 = pack2(dtx, dtx);
            const unsigned long long* Bp = reinterpret_cast<const unsigned long long*>(sB[st]);
#pragma unroll
            for (int sp = 0; sp < DS/2; sp++) {
                h2[sp] = fma2(p2, h2[sp], mul2(dtx2, Bp[sp]));
                p2 = mul2(p2, e22);
            }
        }
        float* He = g_Hend + ((size_t)bc*DI + d)*DS;
#pragma unroll
        for (int sp = 0; sp < DS/2; sp++) {
            float2 v = unpack2(h2[sp]);
            He[2*sp] = v.x; He[2*sp+1] = v.y;
        }
    } else {
        float Av[DS], h[DS];
#pragma unroll
        for (int s = 0; s < DS; s++) { Av[s] = g_A[d*DS + s]; h[s] = 0.f; }
        for (int st = 0; st < CH; st++) {
            float aa = bdt;
#pragma unroll
            for (int r = 0; r < DR; r++) aa += sR[st][r] * wdt[r];
            float dt = softplus_f(aa);
            float x  = g_XC[(size_t)(tok0+st)*DI + d];
            S += dt;
            float dtx = dt * x;
#pragma unroll
            for (int s = 0; s < DS; s++) {
                float a = __expf(dt * Av[s]);
                h[s] = a*h[s] + dtx * sB[st][s];
            }
        }
        float* He = g_Hend + ((size_t)bc*DI + d)*DS;
#pragma unroll
        for (int s = 0; s < DS; s++) He[s] = h[s];
    }
    g_S[(size_t)bc*DI + d] = S;
}

// ---------------- inter-chunk combine ----------------
__global__ __launch_bounds__(256)
void scan_combine()
{
    int g = blockIdx.x * 256 + threadIdx.x;
    int s = g & (DS-1);
    int d = (g >> 4) & (DI-1);
    int b = g >> 12;
    float Av = g_A[d*DS + s];
    float h = 0.f;
    for (int c = 0; c < NC; c++) {
        size_t base = ((size_t)(b*NC + c)*DI + d)*DS + s;
        g_Hin[base] = h;
        float S = g_S[(size_t)(b*NC + c)*DI + d];
        h = __expf(Av * S) * h + g_Hend[base];
    }
}

// ---------------- scan pass 2 (dt inline): y=(scan + xc*D)*silu(z) ----------------
__global__ __launch_bounds__(256)
void scan_pass2(const float* __restrict__ W_dt, const float* __restrict__ b_dt,
                const float* __restrict__ D_param)
{
    __shared__ float sBC[CH][2*DS];
    __shared__ float sR[CH][DR];
    const int bc = blockIdx.x;
    const int b = bc / NC, c = bc % NC;
    const int d = threadIdx.x;
    const int tok0 = b*LL + c*CH;

#pragma unroll
    for (int q = 0; q < (CH*2*DS)/256; q++) {
        int e = threadIdx.x + q*256;
        int j = e & (2*DS - 1), st = e >> 5;
        sBC[st][j] = g_DBL[(size_t)(tok0+st)*40 + 8 + j];
    }
#pragma unroll
    for (int q = 0; q < (CH*DR)/256; q++) {
        int e = threadIdx.x + q*256;
        int r = e & (DR-1), st = e >> 3;
        sR[st][r] = g_DBL[(size_t)(tok0+st)*40 + r];
    }
    __syncthreads();

    float wdt[DR];
#pragma unroll
    for (int r = 0; r < DR; r++) wdt[r] = W_dt[r*DI + d];
    const float bdt = b_dt[d];

    const float A0 = g_A[d*DS];
    const int fast = g_Aflag[d];
    const float Dp = D_param[d];
    const size_t hbase = ((size_t)bc*DI + d)*DS;

    if (fast) {
        unsigned long long h2[DS/2];
#pragma unroll
        for (int sp = 0; sp < DS/2; sp++)
            h2[sp] = pack2(g_Hin[hbase + 2*sp], g_Hin[hbase + 2*sp + 1]);
        for (int st = 0; st < CH; st++) {
            int idx = (tok0+st)*DI + d;
            float aa = bdt;
#pragma unroll
            for (int r = 0; r < DR; r++) aa += sR[st][r] * wdt[r];
            float dt = softplus_f(aa);
            float x  = g_XC[idx];
            float e1 = __expf(dt * A0);
            float e2 = e1 * e1;
            unsigned long long p2  = pack2(e1, e2);
            unsigned long long e22 = pack2(e2, e2);
            float dtx = dt * x;
            unsigned long long dtx2 = pack2(dtx, dtx);
            const unsigned long long* BCp = reinterpret_cast<const unsigned long long*>(sBC[st]);
            unsigned long long y2 = 0ULL;
#pragma unroll
            for (int sp = 0; sp < DS/2; sp++) {
                h2[sp] = fma2(p2, h2[sp], mul2(dtx2, BCp[sp]));
                y2 = fma2(h2[sp], BCp[DS/2 + sp], y2);
                p2 = mul2(p2, e22);
            }
            float2 yv = unpack2(y2);
            float y = yv.x + yv.y;
            float z = g_XZ[(size_t)(tok0+st)*(2*DI) + DI + d];
            float sz = z / (1.f + __expf(-z));
            g_Y[idx] = (y + x*Dp) * sz;
        }
    } else {
        float Av[DS], h[DS];
#pragma unroll
        for (int s = 0; s < DS; s++) { Av[s] = g_A[d*DS + s]; h[s] = g_Hin[hbase + s]; }
        for (int st = 0; st < CH; st++) {
            int idx = (tok0+st)*DI + d;
            float aa = bdt;
#pragma unroll
            for (int r = 0; r < DR; r++) aa += sR[st][r] * wdt[r];
            float dt = softplus_f(aa);
            float x  = g_XC[idx];
            float dtx = dt * x;
            float y = 0.f;
#pragma unroll
            for (int s = 0; s < DS; s++) {
                float a = __expf(dt * Av[s]);
                h[s] = a*h[s] + dtx * sBC[st][s];
                y += h[s] * sBC[st][DS + s];
            }
            float z = g_XZ[(size_t)(tok0+st)*(2*DI) + DI + d];
            float sz = z / (1.f + __expf(-z));
            g_Y[idx] = (y + x*Dp) * sz;
        }
    }
}

// ---------------- host launch ----------------
extern "C" void kernel_launch(void* const* d_in, const int* in_sizes, int n_in,
                              void* d_out, int out_size)
{
    const float* x      = (const float*)d_in[0];
    const float* qk     = (const float*)d_in[1];
    const float* W_mix  = (const float*)d_in[2];
    const float* b_mix  = (const float*)d_in[3];
    const float* W_in   = (const float*)d_in[4];
    const float* b_in   = (const float*)d_in[5];
    const float* conv_w = (const float*)d_in[6];
    const float* conv_b = (const float*)d_in[7];
    const float* W_xproj= (const float*)d_in[8];
    const float* W_dt   = (const float*)d_in[9];
    const float* b_dt   = (const float*)d_in[10];
    const float* A_log  = (const float*)d_in[11];
    const float* D_param= (const float*)d_in[12];
    const float* W_op   = (const float*)d_in[13];
    const float* b_op   = (const float*)d_in[14];
    const float* W_out  = (const float*)d_in[15];
    const float* b_out  = (const float*)d_in[16];
    float* out = (float*)d_out;

    // symbol addresses
    float *pH,*pXZ,*pXC,*pDBL,*pY,*pO1;
    __nv_bfloat16 *pWmixh,*pWmixl,*pWinh,*pWinl,*pWxph,*pWxpl,*pWoph,*pWopl,*pWouth,*pWoutl;
    cudaGetSymbolAddress((void**)&pH,  g_H);
    cudaGetSymbolAddress((void**)&pXZ, g_XZ);
    cudaGetSymbolAddress((void**)&pXC, g_XC);
    cudaGetSymbolAddress((void**)&pDBL,g_DBL);
    cudaGetSymbolAddress((void**)&pY,  g_Y);
    cudaGetSymbolAddress((void**)&pO1, g_O1);
    cudaGetSymbolAddress((void**)&pWmixh, g_Wmix_h);cudaGetSymbolAddress((void**)&pWmixl, g_Wmix_l);
    cudaGetSymbolAddress((void**)&pWinh, g_Win_h);  cudaGetSymbolAddress((void**)&pWinl, g_Win_l);
    cudaGetSymbolAddress((void**)&pWxph, g_Wxp_h);  cudaGetSymbolAddress((void**)&pWxpl, g_Wxp_l);
    cudaGetSymbolAddress((void**)&pWoph, g_Wop_h);  cudaGetSymbolAddress((void**)&pWopl, g_Wop_l);
    cudaGetSymbolAddress((void**)&pWouth, g_Wout_h);cudaGetSymbolAddress((void**)&pWoutl, g_Wout_l);

    constexpr int SM128 = 4*(64*40*2) + 4*(128*40*2);   // A + B buffers: 61440
    constexpr int SM64  = 4*(64*40*2) + 4*(64*40*2);    // 40960
    cudaFuncSetAttribute(gemm_mma<128,true>,  cudaFuncAttributeMaxDynamicSharedMemorySize, SM128);
    cudaFuncSetAttribute(gemm_mma<128,false>, cudaFuncAttributeMaxDynamicSharedMemorySize, SM128);
    cudaFuncSetAttribute(gemm_mma<64,false>,  cudaFuncAttributeMaxDynamicSharedMemorySize, SM64);

    // launches 0-4: prep needed before gemm1 (so ncu -s 5 -c 1 captures gemm_mma)
    aprep_kernel<<<1, 256>>>(A_log);
    wprep_kernel<<<(128*512+255)/256, 256>>>(W_mix,  pWmixh, pWmixl, 512, 128, 128);
    wprep_kernel<<<(512*128+255)/256, 256>>>(W_in,   pWinh,  pWinl,  128, 512, 512);
    wprep_kernel<<<(64*256+255)/256,  256>>>(W_xproj,pWxph,  pWxpl,  256, 40,  64);
    wprep_kernel<<<(128*256+255)/256, 256>>>(W_op,   pWoph,  pWopl,  256, 128, 128);

    // launch 5: H = [x|qk] @ W_mix + b_mix    (K=512, N=128)  <- ncu target
    gemm_mma<128,true><<<dim3(TT/64, 1), 256, SM128>>>(
        x, qk, pWmixh, pWmixl, b_mix, pH, 512, DM, DM);

    // remaining weight prep (needed before final gemm only)
    wprep_kernel<<<(256*128+255)/256, 256>>>(W_out,  pWouth, pWoutl, 128, 256, 256);

    // 2) XZ = H @ W_in + b_in                 (K=128, N=512)
    gemm_mma<128,false><<<dim3(TT/64, 4), 256, SM128>>>(
        pH, nullptr, pWinh, pWinl, b_in, pXZ, 128, 2*DI, 2*DI);

    // 3) conv + silu -> XC
    conv_silu_kernel<<<(TT*DI)/256, 256>>>(conv_w, conv_b);

    // 4) DBL = XC @ W_xproj                   (K=256, N=40 padded 64)
    gemm_mma<64,false><<<dim3(TT/64, 1), 256, SM64>>>(
        pXC, nullptr, pWxph, pWxpl, nullptr, pDBL, 256, 40, 40);

    // 5-7) chunked selective scan (dt fused into both passes)
    scan_pass1  <<<BB*NC, 256>>>(W_dt, b_dt);
    scan_combine<<<(BB*DI*DS)/256, 256>>>();
    scan_pass2  <<<BB*NC, 256>>>(W_dt, b_dt, D_param);

    // 8) O1 = Y @ W_op + b_op                 (K=256, N=128)
    gemm_mma<128,false><<<dim3(TT/64, 1), 256, SM128>>>(
        pY, nullptr, pWoph, pWopl, b_op, pO1, 256, DM, DM);

    // 9) out = O1 @ W_out + b_out             (K=128, N=256)
    gemm_mma<128,false><<<dim3(TT/64, 2), 256, SM128>>>(
        pO1, nullptr, pWouth, pWoutl, b_out, out, 128, CC, CC);
}